// round 3
// baseline (speedup 1.0000x reference)
#include <cuda_runtime.h>
#include <cstdint>

// SimpleGNN (2-layer GCN), N=200000 nodes (10 feat), E=6.4M edges.
// edge_index is INT32 (jax x64 disabled).
// Strategy:
//  - deg pass (int atomics) -> dinv = rsqrt(deg+1)
//  - layer1 aggregate-first: A_hat(x W1) = (A_hat x) W1, so scatter the
//    10-wide raw features (pre-scaled by dinv[src]) instead of 16-wide h.
//  - per-node: t = dinv*(acc1+xs); h1 = relu(t@W1+b1); g = (h1@W2)*dinv
//  - layer2 scatter g (2-wide v2 red), out = dinv*(acc2+g) + b2
// Scratch in __device__ globals; kernel launches only (graph-capturable).

#define MAXN 200000
#define ROWP 12   // padded row stride for 10 features (48B: 16B-aligned v4s)

__device__ float d_xs  [(size_t)MAXN * ROWP];
__device__ float d_acc1[(size_t)MAXN * ROWP];
__device__ float d_dinv[MAXN];
__device__ float d_g   [(size_t)MAXN * 2];
__device__ float d_acc2[(size_t)MAXN * 2];
__device__ int   d_deg [MAXN];

__device__ __forceinline__ void red_add_v4(float* p, float4 v) {
    asm volatile("red.global.add.v4.f32 [%0], {%1,%2,%3,%4};"
                 :: "l"(p), "f"(v.x), "f"(v.y), "f"(v.z), "f"(v.w) : "memory");
}
__device__ __forceinline__ void red_add_v2(float* p, float2 v) {
    asm volatile("red.global.add.v2.f32 [%0], {%1,%2};"
                 :: "l"(p), "f"(v.x), "f"(v.y) : "memory");
}

// Zero accumulators + degree counters (every launch: graph replays).
__global__ __launch_bounds__(256) void k_zero(int n) {
    int i = blockIdx.x * blockDim.x + threadIdx.x;
    if (i < n * ROWP) d_acc1[i] = 0.0f;
    if (i < n * 2)    d_acc2[i] = 0.0f;
    if (i < n)        d_deg[i]  = 0;
}

// In-degree over edges (self-loop added analytically as +1 later).
__global__ __launch_bounds__(256) void k_deg(const int* __restrict__ dst, int E) {
    int e = blockIdx.x * blockDim.x + threadIdx.x;
    if (e < E) atomicAdd(&d_deg[dst[e]], 1);
}

// dinv + pre-scaled source features xs = x * dinv (padded to ROWP).
__global__ __launch_bounds__(256) void k_scale(const float* __restrict__ x, int n) {
    int i = blockIdx.x * blockDim.x + threadIdx.x;
    if (i >= n) return;
    float dv = rsqrtf((float)(d_deg[i] + 1));
    d_dinv[i] = dv;
    const float* xi = x + (size_t)i * 10;
    float* xo = d_xs + (size_t)i * ROWP;
#pragma unroll
    for (int k = 0; k < 10; k++) xo[k] = xi[k] * dv;
    xo[10] = 0.0f; xo[11] = 0.0f;
}

// Layer-1 edge scatter: acc1[dst] += xs[src]   (10 floats: v4+v4+v2 reds)
__global__ __launch_bounds__(256) void k_scat1(const int* __restrict__ idx, int E) {
    int e = blockIdx.x * blockDim.x + threadIdx.x;
    if (e >= E) return;
    int s = idx[e];
    int d = idx[(size_t)E + e];
    const float* ps = d_xs + (size_t)s * ROWP;
    float4 a = *(const float4*)(ps);
    float4 b = *(const float4*)(ps + 4);
    float2 c = *(const float2*)(ps + 8);
    float* pd = d_acc1 + (size_t)d * ROWP;
    red_add_v4(pd,     a);
    red_add_v4(pd + 4, b);
    red_add_v2(pd + 8, c);
}

// Per-node: finish layer-1 aggregation, W1/b1+ReLU, W2, pre-scale by dinv.
__global__ __launch_bounds__(256) void k_node(const float* __restrict__ W1,
                                              const float* __restrict__ b1,
                                              const float* __restrict__ W2, int n) {
    __shared__ float sW1[160], sb1[16], sW2[32];
    int t = threadIdx.x;
    if (t < 160) sW1[t] = W1[t];
    if (t < 16)  sb1[t] = b1[t];
    if (t < 32)  sW2[t] = W2[t];
    __syncthreads();
    int i = blockIdx.x * blockDim.x + t;
    if (i >= n) return;
    float dv = d_dinv[i];
    const float* pa = d_acc1 + (size_t)i * ROWP;
    const float* px = d_xs   + (size_t)i * ROWP;
    float tt[10];
#pragma unroll
    for (int k = 0; k < 10; k++) tt[k] = (pa[k] + px[k]) * dv;  // = (A_hat x)[i]
    float g0 = 0.0f, g1 = 0.0f;
#pragma unroll
    for (int j = 0; j < 16; j++) {
        float h = sb1[j];
#pragma unroll
        for (int k = 0; k < 10; k++) h = fmaf(tt[k], sW1[k * 16 + j], h);
        h = fmaxf(h, 0.0f);                 // relu(h1)
        g0 = fmaf(h, sW2[j * 2 + 0], g0);
        g1 = fmaf(h, sW2[j * 2 + 1], g1);
    }
    d_g[2 * (size_t)i + 0] = g0 * dv;       // pre-scaled source msg for layer 2
    d_g[2 * (size_t)i + 1] = g1 * dv;
}

// Layer-2 edge scatter: acc2[dst] += g[src]   (v2 red)
__global__ __launch_bounds__(256) void k_scat2(const int* __restrict__ idx, int E) {
    int e = blockIdx.x * blockDim.x + threadIdx.x;
    if (e >= E) return;
    int s = idx[e];
    int d = idx[(size_t)E + e];
    float2 v = *(const float2*)(d_g + 2 * (size_t)s);
    red_add_v2(d_acc2 + 2 * (size_t)d, v);
}

// Final: out = dinv*(acc2 + self) + b2
__global__ __launch_bounds__(256) void k_out(const float* __restrict__ b2,
                                             float* __restrict__ out, int n) {
    int i = blockIdx.x * blockDim.x + threadIdx.x;
    if (i >= n) return;
    float dv = d_dinv[i];
    float bb0 = __ldg(b2), bb1 = __ldg(b2 + 1);
    out[2 * (size_t)i + 0] = dv * (d_acc2[2 * (size_t)i + 0] + d_g[2 * (size_t)i + 0]) + bb0;
    out[2 * (size_t)i + 1] = dv * (d_acc2[2 * (size_t)i + 1] + d_g[2 * (size_t)i + 1]) + bb1;
}

extern "C" void kernel_launch(void* const* d_in, const int* in_sizes, int n_in,
                              void* d_out, int out_size) {
    const float* x  = (const float*)d_in[0];
    const int*   ei = (const int*)d_in[1];     // int32: jax x64 disabled
    const float* W1 = (const float*)d_in[2];
    const float* b1 = (const float*)d_in[3];
    const float* W2 = (const float*)d_in[4];
    const float* b2 = (const float*)d_in[5];
    float* out = (float*)d_out;

    int n = in_sizes[0] / 10;
    int E = in_sizes[1] / 2;

    const int TB = 256;
    int gz = (n * ROWP + TB - 1) / TB;
    int ge = (E + TB - 1) / TB;
    int gn = (n + TB - 1) / TB;

    k_zero <<<gz, TB>>>(n);
    k_deg  <<<ge, TB>>>(ei + E, E);     // dst row of edge_index
    k_scale<<<gn, TB>>>(x, n);
    k_scat1<<<ge, TB>>>(ei, E);
    k_node <<<gn, TB>>>(W1, b1, W2, n);
    k_scat2<<<ge, TB>>>(ei, E);
    k_out  <<<gn, TB>>>(b2, out, n);
}

// round 4
// speedup vs baseline: 1.6074x; 1.6074x over previous
#include <cuda_runtime.h>
#include <cuda_fp16.h>
#include <cstdint>

// SimpleGNN (2-layer GCN), N=200000 nodes (10 feat), E=6.4M edges, idx int32.
//  - deg pass (int red) -> dinv = rsqrt(deg+1)
//  - layer1 aggregate-first: A_hat(x W1) = (A_hat x) W1: scatter 10-wide raw
//    features pre-scaled by dinv[src]. Gather payload stored FP16 (32B row:
//    LDG.128 + LDG.32 = 2 L1TEX wavefronts instead of 3); reds stay FP32.
//  - per-node: t = dinv*(acc1+self); h1 = relu(t@W1+b1); g = (h1@W2)*dinv
//  - layer2 scatter g (8B gather + v2 red), out = dinv*(acc2+g) + b2
// Scratch in __device__ globals; kernel launches only (graph-capturable).

#define MAXN 200000
#define ROWP 12     // acc1 row stride in floats (48B, 16B-aligned)
#define XH   16     // xs row stride in halves (32B, 16B-aligned)

__device__ __half d_xsh [(size_t)MAXN * XH];
__device__ float  d_xs32[(size_t)MAXN * ROWP];   // fp32 self-term (exact)
__device__ float  d_acc1[(size_t)MAXN * ROWP];
__device__ float  d_dinv[MAXN];
__device__ float  d_g   [(size_t)MAXN * 2];
__device__ float  d_acc2[(size_t)MAXN * 2];
__device__ int    d_deg [MAXN];

__device__ __forceinline__ void red_add_v4(float* p, float4 v) {
    asm volatile("red.global.add.v4.f32 [%0], {%1,%2,%3,%4};"
                 :: "l"(p), "f"(v.x), "f"(v.y), "f"(v.z), "f"(v.w) : "memory");
}
__device__ __forceinline__ void red_add_v2(float* p, float2 v) {
    asm volatile("red.global.add.v2.f32 [%0], {%1,%2};"
                 :: "l"(p), "f"(v.x), "f"(v.y) : "memory");
}

// Zero accumulators + degree counters (every launch: graph replays).
__global__ __launch_bounds__(256) void k_zero(int n) {
    int i = blockIdx.x * blockDim.x + threadIdx.x;
    if (i < n * ROWP) d_acc1[i] = 0.0f;
    if (i < n * 2)    d_acc2[i] = 0.0f;
    if (i < n)        d_deg[i]  = 0;
}

// In-degree over edges (self-loop added analytically as +1 later).
__global__ __launch_bounds__(256) void k_deg(const int* __restrict__ dst, int E) {
    int e = blockIdx.x * blockDim.x + threadIdx.x;
    if (e < E) atomicAdd(&d_deg[dst[e]], 1);
}

// dinv + pre-scaled source features: fp16 copy (for edge gather) and fp32
// copy (for the exact self term in k_node).
__global__ __launch_bounds__(256) void k_scale(const float* __restrict__ x, int n) {
    int i = blockIdx.x * blockDim.x + threadIdx.x;
    if (i >= n) return;
    float dv = rsqrtf((float)(d_deg[i] + 1));
    d_dinv[i] = dv;
    const float* xi = x + (size_t)i * 10;
    float* xo = d_xs32 + (size_t)i * ROWP;
    float v[10];
#pragma unroll
    for (int k = 0; k < 10; k++) { v[k] = xi[k] * dv; xo[k] = v[k]; }
    // pack 10 halves: one 16B store + one 4B store
    __half2 h[5];
#pragma unroll
    for (int k = 0; k < 5; k++) h[k] = __floats2half2_rn(v[2 * k], v[2 * k + 1]);
    uint4 pk;
    pk.x = *(uint32_t*)&h[0]; pk.y = *(uint32_t*)&h[1];
    pk.z = *(uint32_t*)&h[2]; pk.w = *(uint32_t*)&h[3];
    *(uint4*)(d_xsh + (size_t)i * XH) = pk;
    *(uint32_t*)(d_xsh + (size_t)i * XH + 8) = *(uint32_t*)&h[4];
}

// Layer-1 edge scatter: acc1[dst] += xs[src].
// Gather: LDG.128 + LDG.32 (fp16) = 2 wavefronts; red: v4+v4+v2 fp32 = 3.
__global__ __launch_bounds__(256) void k_scat1(const int* __restrict__ idx, int E) {
    int e = blockIdx.x * blockDim.x + threadIdx.x;
    if (e >= E) return;
    int s = idx[e];
    int d = idx[(size_t)E + e];
    const __half* ps = d_xsh + (size_t)s * XH;
    uint4    a = *(const uint4*)(ps);
    uint32_t b = *(const uint32_t*)(ps + 8);
    float2 f0 = __half22float2(*(__half2*)&a.x);
    float2 f1 = __half22float2(*(__half2*)&a.y);
    float2 f2 = __half22float2(*(__half2*)&a.z);
    float2 f3 = __half22float2(*(__half2*)&a.w);
    float2 f4 = __half22float2(*(__half2*)&b);
    float* pd = d_acc1 + (size_t)d * ROWP;
    red_add_v4(pd,     make_float4(f0.x, f0.y, f1.x, f1.y));
    red_add_v4(pd + 4, make_float4(f2.x, f2.y, f3.x, f3.y));
    red_add_v2(pd + 8, make_float2(f4.x, f4.y));
}

// Per-node: finish layer-1 aggregation, W1/b1+ReLU, W2, pre-scale by dinv.
__global__ __launch_bounds__(256) void k_node(const float* __restrict__ W1,
                                              const float* __restrict__ b1,
                                              const float* __restrict__ W2, int n) {
    __shared__ float sW1[160], sb1[16], sW2[32];
    int t = threadIdx.x;
    if (t < 160) sW1[t] = W1[t];
    if (t < 16)  sb1[t] = b1[t];
    if (t < 32)  sW2[t] = W2[t];
    __syncthreads();
    int i = blockIdx.x * blockDim.x + t;
    if (i >= n) return;
    float dv = d_dinv[i];
    const float* pa = d_acc1 + (size_t)i * ROWP;
    const float* px = d_xs32 + (size_t)i * ROWP;
    float tt[10];
#pragma unroll
    for (int k = 0; k < 10; k++) tt[k] = (pa[k] + px[k]) * dv;  // = (A_hat x)[i]
    float g0 = 0.0f, g1 = 0.0f;
#pragma unroll
    for (int j = 0; j < 16; j++) {
        float h = sb1[j];
#pragma unroll
        for (int k = 0; k < 10; k++) h = fmaf(tt[k], sW1[k * 16 + j], h);
        h = fmaxf(h, 0.0f);                 // relu(h1)
        g0 = fmaf(h, sW2[j * 2 + 0], g0);
        g1 = fmaf(h, sW2[j * 2 + 1], g1);
    }
    d_g[2 * (size_t)i + 0] = g0 * dv;       // pre-scaled source msg for layer 2
    d_g[2 * (size_t)i + 1] = g1 * dv;
}

// Layer-2 edge scatter: acc2[dst] += g[src]   (LDG.64 gather + v2 red)
__global__ __launch_bounds__(256) void k_scat2(const int* __restrict__ idx, int E) {
    int e = blockIdx.x * blockDim.x + threadIdx.x;
    if (e >= E) return;
    int s = idx[e];
    int d = idx[(size_t)E + e];
    float2 v = *(const float2*)(d_g + 2 * (size_t)s);
    red_add_v2(d_acc2 + 2 * (size_t)d, v);
}

// Final: out = dinv*(acc2 + self) + b2
__global__ __launch_bounds__(256) void k_out(const float* __restrict__ b2,
                                             float* __restrict__ out, int n) {
    int i = blockIdx.x * blockDim.x + threadIdx.x;
    if (i >= n) return;
    float dv = d_dinv[i];
    float bb0 = __ldg(b2), bb1 = __ldg(b2 + 1);
    out[2 * (size_t)i + 0] = dv * (d_acc2[2 * (size_t)i + 0] + d_g[2 * (size_t)i + 0]) + bb0;
    out[2 * (size_t)i + 1] = dv * (d_acc2[2 * (size_t)i + 1] + d_g[2 * (size_t)i + 1]) + bb1;
}

extern "C" void kernel_launch(void* const* d_in, const int* in_sizes, int n_in,
                              void* d_out, int out_size) {
    const float* x  = (const float*)d_in[0];
    const int*   ei = (const int*)d_in[1];     // int32 (jax x64 disabled)
    const float* W1 = (const float*)d_in[2];
    const float* b1 = (const float*)d_in[3];
    const float* W2 = (const float*)d_in[4];
    const float* b2 = (const float*)d_in[5];
    float* out = (float*)d_out;

    int n = in_sizes[0] / 10;
    int E = in_sizes[1] / 2;

    const int TB = 256;
    int gz = (n * ROWP + TB - 1) / TB;
    int ge = (E + TB - 1) / TB;
    int gn = (n + TB - 1) / TB;

    k_zero <<<gz, TB>>>(n);
    k_deg  <<<ge, TB>>>(ei + E, E);     // dst row of edge_index
    k_scale<<<gn, TB>>>(x, n);
    k_scat1<<<ge, TB>>>(ei, E);
    k_node <<<gn, TB>>>(W1, b1, W2, n);
    k_scat2<<<ge, TB>>>(ei, E);
    k_out  <<<gn, TB>>>(b2, out, n);
}